// round 3
// baseline (speedup 1.0000x reference)
#include <cuda_runtime.h>

// ---------------------------------------------------------------------------
// GAT (2-layer GATConv), N=50000, E=850000 (incl self-loops), F=128, H=4, D=32
//   1. counting-sort edges by dst (hist -> scan -> scatter), reused twice
//   2. per layer: f32x2-packed GEMM feat = X@W with fused el/er epilogue
//   3. per layer: flat edge kernel (exp scores + atomic per-(dst,head) sums,
//      no max pass — softmax is shift-invariant and scores are O(1))
//   4. per layer: warp-per-dst-node weighted float4 gather (no atomics)
// ---------------------------------------------------------------------------

#define FULL 0xffffffffu
typedef unsigned long long ull;

constexpr int NN = 50000;
constexpr int EE = 850000;
constexpr int FH = 128;   // H*D
constexpr int HH = 4;
constexpr int SCAN_B = 1024;
constexpr int SCAN_NB = (NN + SCAN_B - 1) / SCAN_B;   // 49

// scratch (device globals; no allocation allowed)
__device__ float g_feat[NN * FH];
__device__ float g_hid[NN * FH];
__device__ float g_el[NN * HH];
__device__ float g_er[NN * HH];
__device__ float g_sum[NN * HH];
__device__ float g_esc[EE * HH];
__device__ int   g_counts[NN];
__device__ int   g_cursor[NN];
__device__ int   g_off[NN + 1];
__device__ int   g_excl[NN];
__device__ int   g_bsum[64];
__device__ int   g_bsumoff[64];
__device__ int   g_ssrc[EE];
__device__ int   g_sdst[EE];

// ---------------------------------------------------------------------------
__device__ __forceinline__ ull pack2(float lo, float hi) {
    ull r; asm("mov.b64 %0, {%1,%2};" : "=l"(r) : "f"(lo), "f"(hi)); return r;
}
__device__ __forceinline__ float2 unpack2(ull v) {
    float2 r; asm("mov.b64 {%0,%1}, %2;" : "=f"(r.x), "=f"(r.y) : "l"(v)); return r;
}
__device__ __forceinline__ void ffma2(ull& d, ull a, ull b) {
    asm("fma.rn.f32x2 %0, %1, %2, %0;" : "+l"(d) : "l"(a), "l"(b));
}
__device__ __forceinline__ float lk(float x, float s) { return x > 0.f ? x : x * s; }

// ---------------------------------------------------------------------------
__global__ void k_init() {
    int i = blockIdx.x * blockDim.x + threadIdx.x;
    if (i < NN) {
        g_counts[i] = 0; g_cursor[i] = 0;
        float4* s4 = reinterpret_cast<float4*>(g_sum);
        s4[i] = make_float4(0.f, 0.f, 0.f, 0.f);
    }
}

__global__ void k_hist(const int* __restrict__ dst) {
    int i = blockIdx.x * blockDim.x + threadIdx.x;
    if (i < EE) atomicAdd(&g_counts[dst[i]], 1);
}

__global__ void k_scan_blocks() {
    __shared__ int sh[SCAN_B];
    int g = blockIdx.x * SCAN_B + threadIdx.x;
    int v = (g < NN) ? g_counts[g] : 0;
    sh[threadIdx.x] = v;
    __syncthreads();
    for (int o = 1; o < SCAN_B; o <<= 1) {
        int t = (threadIdx.x >= o) ? sh[threadIdx.x - o] : 0;
        __syncthreads();
        sh[threadIdx.x] += t;
        __syncthreads();
    }
    if (g < NN) g_excl[g] = sh[threadIdx.x] - v;
    if (threadIdx.x == SCAN_B - 1) g_bsum[blockIdx.x] = sh[SCAN_B - 1];
}

__global__ void k_scan_bsums() {
    __shared__ int sh[64];
    int t = threadIdx.x;
    int v = (t < SCAN_NB) ? g_bsum[t] : 0;
    sh[t] = v;
    __syncthreads();
    for (int o = 1; o < 64; o <<= 1) {
        int u = (t >= o) ? sh[t - o] : 0;
        __syncthreads();
        sh[t] += u;
        __syncthreads();
    }
    if (t < SCAN_NB) g_bsumoff[t] = sh[t] - v;
}

__global__ void k_scan_add() {
    int g = blockIdx.x * SCAN_B + threadIdx.x;
    if (g < NN) g_off[g] = g_excl[g] + g_bsumoff[blockIdx.x];
    if (g == 0) g_off[NN] = EE;
}

__global__ void k_scatter(const int* __restrict__ src, const int* __restrict__ dst) {
    int i = blockIdx.x * blockDim.x + threadIdx.x;
    if (i < EE) {
        int v = dst[i];
        int pos = g_off[v] + atomicAdd(&g_cursor[v], 1);
        g_ssrc[pos] = src[i];
        g_sdst[pos] = v;
    }
}

// ---------------------------------------------------------------------------
// GEMM: feat[N,128] = X[N,128] @ W[128,128] using packed fma.rn.f32x2.
// 256 threads / 8 warps, 128 rows/block. Warp: 16 rows (8 row-pairs) x 128
// cols (4 cols/lane). X tile stored k-major so a row-pair is one LDS.64
// that is directly a packed f32x2 operand. Fused el/er epilogue.
// ---------------------------------------------------------------------------
__global__ void __launch_bounds__(256) k_gemm(
        const float* __restrict__ X, const float* __restrict__ W,
        const float* __restrict__ al, const float* __restrict__ ar) {
    constexpr int GR = 128, KC = 32, XP = GR + 2;   // pitch 130: bank=(2k+r)%32
    __shared__ float Wsh[KC][FH];
    __shared__ float Xsh[KC][XP];

    int tid = threadIdx.x, lane = tid & 31, warp = tid >> 5;
    int row0 = blockIdx.x * GR;

    ull acc[8][4];
#pragma unroll
    for (int rp = 0; rp < 8; rp++)
#pragma unroll
        for (int c = 0; c < 4; c++) acc[rp][c] = 0ull;

    const float4* W4 = reinterpret_cast<const float4*>(W);
    const float4* X4 = reinterpret_cast<const float4*>(X);

    for (int kc = 0; kc < FH; kc += KC) {
        // W tile: [k][col], thread: k=t>>3, 4 float4 chunks
        {
            int k = tid >> 3, q = tid & 7;
#pragma unroll
            for (int j = 0; j < 4; j++) {
                float4 w = W4[(kc + k) * 32 + q + 8 * j];
                *reinterpret_cast<float4*>(&Wsh[k][(q + 8 * j) * 4]) = w;
            }
        }
        // X tile transposed: thread loads float4 of row (r), writes 4 scalars
        {
            int c = tid & 7, rb = tid >> 3;   // c: which float4 of 32 k, rb: 0..31
#pragma unroll
            for (int m = 0; m < 4; m++) {
                int r = rb + 32 * m;
                int row = row0 + r;
                float4 xv = (row < NN) ? X4[row * 32 + (kc >> 2) + c]
                                       : make_float4(0.f, 0.f, 0.f, 0.f);
                Xsh[4 * c + 0][r] = xv.x;
                Xsh[4 * c + 1][r] = xv.y;
                Xsh[4 * c + 2][r] = xv.z;
                Xsh[4 * c + 3][r] = xv.w;
            }
        }
        __syncthreads();

#pragma unroll 4
        for (int k = 0; k < KC; k++) {
            float4 w = *reinterpret_cast<const float4*>(&Wsh[k][lane * 4]);
            ull w0 = pack2(w.x, w.x), w1 = pack2(w.y, w.y);
            ull w2 = pack2(w.z, w.z), w3 = pack2(w.w, w.w);
            const ull* arow = reinterpret_cast<const ull*>(&Xsh[k][warp * 16]);
#pragma unroll
            for (int rp = 0; rp < 8; rp++) {
                ull a2 = arow[rp];
                ffma2(acc[rp][0], a2, w0);
                ffma2(acc[rp][1], a2, w1);
                ffma2(acc[rp][2], a2, w2);
                ffma2(acc[rp][3], a2, w3);
            }
        }
        __syncthreads();
    }

    // epilogue: store feat + fused el/er (8-lane segmented reduction per head)
    int h = lane >> 3;
    float4 alv = reinterpret_cast<const float4*>(al)[h * 8 + (lane & 7)];
    float4 arv = reinterpret_cast<const float4*>(ar)[h * 8 + (lane & 7)];
    float4* feat4 = reinterpret_cast<float4*>(g_feat);

#pragma unroll
    for (int rp = 0; rp < 8; rp++) {
        float2 c0 = unpack2(acc[rp][0]), c1 = unpack2(acc[rp][1]);
        float2 c2 = unpack2(acc[rp][2]), c3 = unpack2(acc[rp][3]);
        int rlo = row0 + warp * 16 + rp * 2;
        int rhi = rlo + 1;
        if (rlo < NN) feat4[rlo * 32 + lane] = make_float4(c0.x, c1.x, c2.x, c3.x);
        if (rhi < NN) feat4[rhi * 32 + lane] = make_float4(c0.y, c1.y, c2.y, c3.y);

        float el_lo = c0.x * alv.x + c1.x * alv.y + c2.x * alv.z + c3.x * alv.w;
        float er_lo = c0.x * arv.x + c1.x * arv.y + c2.x * arv.z + c3.x * arv.w;
        float el_hi = c0.y * alv.x + c1.y * alv.y + c2.y * alv.z + c3.y * alv.w;
        float er_hi = c0.y * arv.x + c1.y * arv.y + c2.y * arv.z + c3.y * arv.w;
#pragma unroll
        for (int o = 4; o; o >>= 1) {
            el_lo += __shfl_xor_sync(FULL, el_lo, o);
            er_lo += __shfl_xor_sync(FULL, er_lo, o);
            el_hi += __shfl_xor_sync(FULL, el_hi, o);
            er_hi += __shfl_xor_sync(FULL, er_hi, o);
        }
        if ((lane & 7) == 0) {
            if (rlo < NN) { g_el[rlo * HH + h] = el_lo; g_er[rlo * HH + h] = er_lo; }
            if (rhi < NN) { g_el[rhi * HH + h] = el_hi; g_er[rhi * HH + h] = er_hi; }
        }
    }
}

// ---------------------------------------------------------------------------
// Flat edge kernel: one thread per (sorted) edge.
// ex = exp(leaky(el[src]+er[dst], 0.2)); store ex; atomic per-(dst,head) sum.
// No max subtraction: scores are O(1), softmax is shift-invariant.
// ---------------------------------------------------------------------------
__global__ void k_edge() {
    int i = blockIdx.x * blockDim.x + threadIdx.x;
    if (i >= EE) return;
    int s = g_ssrc[i], d = g_sdst[i];
    float4 el = reinterpret_cast<const float4*>(g_el)[s];
    float4 er = reinterpret_cast<const float4*>(g_er)[d];
    float4 ex;
    ex.x = __expf(lk(el.x + er.x, 0.2f));
    ex.y = __expf(lk(el.y + er.y, 0.2f));
    ex.z = __expf(lk(el.z + er.z, 0.2f));
    ex.w = __expf(lk(el.w + er.w, 0.2f));
    reinterpret_cast<float4*>(g_esc)[i] = ex;
    atomicAdd(&g_sum[d * 4 + 0], ex.x);
    atomicAdd(&g_sum[d * 4 + 1], ex.y);
    atomicAdd(&g_sum[d * 4 + 2], ex.z);
    atomicAdd(&g_sum[d * 4 + 3], ex.w);
}

// Like k_edge but also re-zeroes g_sum for the NEXT layer's accumulation is
// not possible (sum read after); instead gather kernel consumes g_sum and a
// separate tiny reset runs between layers.
__global__ void k_zero_sum() {
    int i = blockIdx.x * blockDim.x + threadIdx.x;
    if (i < NN) reinterpret_cast<float4*>(g_sum)[i] = make_float4(0.f, 0.f, 0.f, 0.f);
}

// ---------------------------------------------------------------------------
// Gather kernel: one warp per dst node.
// acc += (ex/sum) * feat[src]  (float4/lane, 4-way edge unroll), + bias, act.
// ---------------------------------------------------------------------------
__global__ void k_gather(const float* __restrict__ bias, float* __restrict__ out,
                         float act_slope, int apply_act) {
    int wg = (blockIdx.x * blockDim.x + threadIdx.x) >> 5;
    int lane = threadIdx.x & 31;
    if (wg >= NN) return;
    int v = wg;
    int start = g_off[v], end = g_off[v + 1];

    const float4* feat4 = reinterpret_cast<const float4*>(g_feat);
    const float* escf = g_esc;

    int h = lane >> 3;
    float inv = 1.f / g_sum[v * 4 + h];

    float4 a0 = make_float4(0, 0, 0, 0), a1 = a0, a2 = a0, a3 = a0;
    int p = start;
#define STEP(PP, ACC)                                           \
    {                                                           \
        int s_ = g_ssrc[PP];                                    \
        float a_ = escf[(PP) * 4 + h] * inv;                    \
        float4 f_ = feat4[s_ * 32 + lane];                      \
        ACC.x = fmaf(a_, f_.x, ACC.x);                          \
        ACC.y = fmaf(a_, f_.y, ACC.y);                          \
        ACC.z = fmaf(a_, f_.z, ACC.z);                          \
        ACC.w = fmaf(a_, f_.w, ACC.w);                          \
    }
    for (; p + 4 <= end; p += 4) {
        STEP(p + 0, a0); STEP(p + 1, a1); STEP(p + 2, a2); STEP(p + 3, a3);
    }
    for (; p < end; ++p) STEP(p, a0);
#undef STEP
    float4 acc;
    acc.x = (a0.x + a1.x) + (a2.x + a3.x);
    acc.y = (a0.y + a1.y) + (a2.y + a3.y);
    acc.z = (a0.z + a1.z) + (a2.z + a3.z);
    acc.w = (a0.w + a1.w) + (a2.w + a3.w);

    float4 b = reinterpret_cast<const float4*>(bias)[lane];
    acc.x += b.x; acc.y += b.y; acc.z += b.z; acc.w += b.w;
    if (apply_act) {
        acc.x = lk(acc.x, act_slope);
        acc.y = lk(acc.y, act_slope);
        acc.z = lk(acc.z, act_slope);
        acc.w = lk(acc.w, act_slope);
    }
    reinterpret_cast<float4*>(out)[v * 32 + lane] = acc;
}

// ---------------------------------------------------------------------------
extern "C" void kernel_launch(void* const* d_in, const int* in_sizes, int n_in,
                              void* d_out, int out_size) {
    const float* x   = (const float*)d_in[0];
    const int*   src = (const int*)d_in[1];
    const int*   dst = (const int*)d_in[2];
    const float* W1  = (const float*)d_in[3];
    const float* al1 = (const float*)d_in[4];
    const float* ar1 = (const float*)d_in[5];
    const float* b1  = (const float*)d_in[6];
    const float* W2  = (const float*)d_in[7];
    const float* al2 = (const float*)d_in[8];
    const float* ar2 = (const float*)d_in[9];
    const float* b2  = (const float*)d_in[10];
    float* out = (float*)d_out;

    void* p_hid = nullptr;
    cudaGetSymbolAddress(&p_hid, g_hid);
    float* hid = (float*)p_hid;

    int eblocks = (EE + 255) / 256;
    int nblocks = (NN + 255) / 256;
    int gemm_blocks = (NN + 127) / 128;
    int gather_blocks = (NN + 7) / 8;   // 8 warps/block

    // CSR build (dst-sorted edges), reused for both layers
    k_init<<<nblocks, 256>>>();
    k_hist<<<eblocks, 256>>>(dst);
    k_scan_blocks<<<SCAN_NB, SCAN_B>>>();
    k_scan_bsums<<<1, 64>>>();
    k_scan_add<<<SCAN_NB, SCAN_B>>>();
    k_scatter<<<eblocks, 256>>>(src, dst);

    // layer 1
    k_gemm<<<gemm_blocks, 256>>>(x, W1, al1, ar1);
    k_edge<<<eblocks, 256>>>();
    k_gather<<<gather_blocks, 256>>>(b1, hid, 0.01f, 1);

    // layer 2
    k_zero_sum<<<nblocks, 256>>>();
    k_gemm<<<gemm_blocks, 256>>>(hid, W2, al2, ar2);
    k_edge<<<eblocks, 256>>>();
    k_gather<<<gather_blocks, 256>>>(b2, out, 0.0f, 0);
}

// round 5
// speedup vs baseline: 1.1821x; 1.1821x over previous
#include <cuda_runtime.h>

// ---------------------------------------------------------------------------
// GAT (2-layer GATConv), N=50000, E=850000 (incl self-loops), F=128, H=4, D=32
// 8 launches total:
//   1 k_init     zero counts/cursors/total
//   2 k_hist     per-dst degree histogram
//   3 k_offsets  block-scan + 1 atomic per block -> contiguous segment per dst
//   4 k_gemm L1  f32x2-packed GEMM feat=X@W, fused el/er epilogue
//   5 k_scatter  bucket edges by dst (CSR), reused by both layers
//   6 k_gather L1  fused edge-softmax + weighted feat gather (warp/node)
//   7 k_gemm L2
//   8 k_gather L2
// ---------------------------------------------------------------------------

#define FULL 0xffffffffu
typedef unsigned long long ull;

constexpr int NN = 50000;
constexpr int EE = 850000;
constexpr int FH = 128;   // H*D
constexpr int HH = 4;

// scratch (device globals; no allocation allowed)
__device__ float g_feat[NN * FH];
__device__ float g_hid[NN * FH];
__device__ float g_el[NN * HH];
__device__ float g_er[NN * HH];
__device__ int   g_counts[NN];
__device__ int   g_cursor[NN];
__device__ int   g_off[NN];
__device__ int   g_total;
__device__ int   g_ssrc[EE];

// ---------------------------------------------------------------------------
__device__ __forceinline__ ull pack2(float lo, float hi) {
    ull r; asm("mov.b64 %0, {%1,%2};" : "=l"(r) : "f"(lo), "f"(hi)); return r;
}
__device__ __forceinline__ float2 unpack2(ull v) {
    float2 r; asm("mov.b64 {%0,%1}, %2;" : "=f"(r.x), "=f"(r.y) : "l"(v)); return r;
}
__device__ __forceinline__ void ffma2(ull& d, ull a, ull b) {
    asm("fma.rn.f32x2 %0, %1, %2, %0;" : "+l"(d) : "l"(a), "l"(b));
}
__device__ __forceinline__ float lk(float x, float s) { return x > 0.f ? x : x * s; }

// ---------------------------------------------------------------------------
__global__ void k_init() {
    int i = blockIdx.x * blockDim.x + threadIdx.x;
    if (i < NN) { g_counts[i] = 0; g_cursor[i] = 0; }
    if (i == 0) g_total = 0;
}

__global__ void k_hist(const int* __restrict__ dst) {
    int i = blockIdx.x * blockDim.x + threadIdx.x;
    if (i < EE) atomicAdd(&g_counts[dst[i]], 1);
}

// Reserve a contiguous segment per node. Segments need NOT be in node order:
// block-exclusive-scan of counts, one atomicAdd on g_total per block for base.
__global__ void k_offsets() {
    __shared__ int wsum[32];
    __shared__ int sbase;
    int i = blockIdx.x * 1024 + threadIdx.x;
    int lane = threadIdx.x & 31, warp = threadIdx.x >> 5;
    int v = (i < NN) ? g_counts[i] : 0;

    // warp inclusive scan
    int incl = v;
#pragma unroll
    for (int o = 1; o < 32; o <<= 1) {
        int t = __shfl_up_sync(FULL, incl, o);
        if (lane >= o) incl += t;
    }
    if (lane == 31) wsum[warp] = incl;
    __syncthreads();
    if (warp == 0) {
        int w = wsum[lane];
#pragma unroll
        for (int o = 1; o < 32; o <<= 1) {
            int t = __shfl_up_sync(FULL, w, o);
            if (lane >= o) w += t;
        }
        wsum[lane] = w;               // inclusive over warp totals
        if (lane == 31) sbase = atomicAdd(&g_total, w);
    }
    __syncthreads();
    int excl = incl - v + (warp ? wsum[warp - 1] : 0);
    if (i < NN) g_off[i] = sbase + excl;
}

__global__ void k_scatter(const int* __restrict__ src, const int* __restrict__ dst) {
    int i = blockIdx.x * blockDim.x + threadIdx.x;
    if (i < EE) {
        int v = dst[i];
        int pos = g_off[v] + atomicAdd(&g_cursor[v], 1);
        g_ssrc[pos] = src[i];
    }
}

// ---------------------------------------------------------------------------
// GEMM: feat[N,128] = X[N,128] @ W[128,128] using packed fma.rn.f32x2.
// 256 threads / 8 warps, 128 rows/block. Warp: 16 rows (8 row-pairs) x 128
// cols (4 cols/lane). X tile stored k-major so a row-pair is one LDS.64
// packed f32x2 operand. Fused el/er epilogue.
// ---------------------------------------------------------------------------
__global__ void __launch_bounds__(256) k_gemm(
        const float* __restrict__ X, const float* __restrict__ W,
        const float* __restrict__ al, const float* __restrict__ ar) {
    constexpr int GR = 128, KC = 32, XP = GR + 2;
    __shared__ float Wsh[KC][FH];
    __shared__ float Xsh[KC][XP];

    int tid = threadIdx.x, lane = tid & 31, warp = tid >> 5;
    int row0 = blockIdx.x * GR;

    ull acc[8][4];
#pragma unroll
    for (int rp = 0; rp < 8; rp++)
#pragma unroll
        for (int c = 0; c < 4; c++) acc[rp][c] = 0ull;

    const float4* W4 = reinterpret_cast<const float4*>(W);
    const float4* X4 = reinterpret_cast<const float4*>(X);

    for (int kc = 0; kc < FH; kc += KC) {
        {
            int k = tid >> 3, q = tid & 7;
#pragma unroll
            for (int j = 0; j < 4; j++) {
                float4 w = W4[(kc + k) * 32 + q + 8 * j];
                *reinterpret_cast<float4*>(&Wsh[k][(q + 8 * j) * 4]) = w;
            }
        }
        {
            int c = tid & 7, rb = tid >> 3;
#pragma unroll
            for (int m = 0; m < 4; m++) {
                int r = rb + 32 * m;
                int row = row0 + r;
                float4 xv = (row < NN) ? X4[row * 32 + (kc >> 2) + c]
                                       : make_float4(0.f, 0.f, 0.f, 0.f);
                Xsh[4 * c + 0][r] = xv.x;
                Xsh[4 * c + 1][r] = xv.y;
                Xsh[4 * c + 2][r] = xv.z;
                Xsh[4 * c + 3][r] = xv.w;
            }
        }
        __syncthreads();

#pragma unroll 4
        for (int k = 0; k < KC; k++) {
            float4 w = *reinterpret_cast<const float4*>(&Wsh[k][lane * 4]);
            ull w0 = pack2(w.x, w.x), w1 = pack2(w.y, w.y);
            ull w2 = pack2(w.z, w.z), w3 = pack2(w.w, w.w);
            const ull* arow = reinterpret_cast<const ull*>(&Xsh[k][warp * 16]);
#pragma unroll
            for (int rp = 0; rp < 8; rp++) {
                ull a2 = arow[rp];
                ffma2(acc[rp][0], a2, w0);
                ffma2(acc[rp][1], a2, w1);
                ffma2(acc[rp][2], a2, w2);
                ffma2(acc[rp][3], a2, w3);
            }
        }
        __syncthreads();
    }

    int h = lane >> 3;
    float4 alv = reinterpret_cast<const float4*>(al)[h * 8 + (lane & 7)];
    float4 arv = reinterpret_cast<const float4*>(ar)[h * 8 + (lane & 7)];
    float4* feat4 = reinterpret_cast<float4*>(g_feat);

#pragma unroll
    for (int rp = 0; rp < 8; rp++) {
        float2 c0 = unpack2(acc[rp][0]), c1 = unpack2(acc[rp][1]);
        float2 c2 = unpack2(acc[rp][2]), c3 = unpack2(acc[rp][3]);
        int rlo = row0 + warp * 16 + rp * 2;
        int rhi = rlo + 1;
        if (rlo < NN) feat4[rlo * 32 + lane] = make_float4(c0.x, c1.x, c2.x, c3.x);
        if (rhi < NN) feat4[rhi * 32 + lane] = make_float4(c0.y, c1.y, c2.y, c3.y);

        float el_lo = c0.x * alv.x + c1.x * alv.y + c2.x * alv.z + c3.x * alv.w;
        float er_lo = c0.x * arv.x + c1.x * arv.y + c2.x * arv.z + c3.x * arv.w;
        float el_hi = c0.y * alv.x + c1.y * alv.y + c2.y * alv.z + c3.y * alv.w;
        float er_hi = c0.y * arv.x + c1.y * arv.y + c2.y * arv.z + c3.y * arv.w;
#pragma unroll
        for (int o = 4; o; o >>= 1) {
            el_lo += __shfl_xor_sync(FULL, el_lo, o);
            er_lo += __shfl_xor_sync(FULL, er_lo, o);
            el_hi += __shfl_xor_sync(FULL, el_hi, o);
            er_hi += __shfl_xor_sync(FULL, er_hi, o);
        }
        if ((lane & 7) == 0) {
            if (rlo < NN) { g_el[rlo * HH + h] = el_lo; g_er[rlo * HH + h] = er_lo; }
            if (rhi < NN) { g_el[rhi * HH + h] = el_hi; g_er[rhi * HH + h] = er_hi; }
        }
    }
}

// ---------------------------------------------------------------------------
// Fused softmax + gather: one warp per dst node. No max-subtraction (scores
// are O(1), softmax is shift-invariant) and no edge-score scratch:
//   pass A: lanes stride edges, sum4 += exp(leaky(el4[src]+er4[v])); reduce.
//   pass B: per edge, recompute a = exp(.)/sum_h, acc += a * feat[src].
// ---------------------------------------------------------------------------
__device__ __forceinline__ float4 wred_sum4(float4 v) {
#pragma unroll
    for (int o = 16; o; o >>= 1) {
        v.x += __shfl_xor_sync(FULL, v.x, o);
        v.y += __shfl_xor_sync(FULL, v.y, o);
        v.z += __shfl_xor_sync(FULL, v.z, o);
        v.w += __shfl_xor_sync(FULL, v.w, o);
    }
    return v;
}

__global__ void k_gather(const float* __restrict__ bias, float* __restrict__ out,
                         float act_slope, int apply_act) {
    int wg = (blockIdx.x * blockDim.x + threadIdx.x) >> 5;
    int lane = threadIdx.x & 31;
    if (wg >= NN) return;
    int v = wg;
    int start = g_off[v];
    int end = start + g_counts[v];

    const float4* feat4 = reinterpret_cast<const float4*>(g_feat);
    const float4* el4 = reinterpret_cast<const float4*>(g_el);
    const float* elf = g_el;

    float4 erv = reinterpret_cast<const float4*>(g_er)[v];

    // pass A: per-head softmax denominators
    float4 sm = make_float4(0.f, 0.f, 0.f, 0.f);
    for (int p = start + lane; p < end; p += 32) {
        int s = g_ssrc[p];
        float4 e = el4[s];
        sm.x += __expf(lk(e.x + erv.x, 0.2f));
        sm.y += __expf(lk(e.y + erv.y, 0.2f));
        sm.z += __expf(lk(e.z + erv.z, 0.2f));
        sm.w += __expf(lk(e.w + erv.w, 0.2f));
    }
    sm = wred_sum4(sm);

    int h = lane >> 3;
    float shd = (h == 0) ? sm.x : (h == 1) ? sm.y : (h == 2) ? sm.z : sm.w;
    float erh = (h == 0) ? erv.x : (h == 1) ? erv.y : (h == 2) ? erv.z : erv.w;
    float inv = 1.f / shd;

    // pass B: weighted gather, 4-way edge unroll
    float4 a0 = make_float4(0, 0, 0, 0), a1 = a0, a2 = a0, a3 = a0;
    int p = start;
#define STEP(PP, ACC)                                            \
    {                                                            \
        int s_ = g_ssrc[PP];                                     \
        float a_ = __expf(lk(elf[s_ * 4 + h] + erh, 0.2f)) * inv;\
        float4 f_ = feat4[s_ * 32 + lane];                       \
        ACC.x = fmaf(a_, f_.x, ACC.x);                           \
        ACC.y = fmaf(a_, f_.y, ACC.y);                           \
        ACC.z = fmaf(a_, f_.z, ACC.z);                           \
        ACC.w = fmaf(a_, f_.w, ACC.w);                           \
    }
    for (; p + 4 <= end; p += 4) {
        STEP(p + 0, a0); STEP(p + 1, a1); STEP(p + 2, a2); STEP(p + 3, a3);
    }
    for (; p < end; ++p) STEP(p, a0);
#undef STEP
    float4 acc;
    acc.x = (a0.x + a1.x) + (a2.x + a3.x);
    acc.y = (a0.y + a1.y) + (a2.y + a3.y);
    acc.z = (a0.z + a1.z) + (a2.z + a3.z);
    acc.w = (a0.w + a1.w) + (a2.w + a3.w);

    float4 b = reinterpret_cast<const float4*>(bias)[lane];
    acc.x += b.x; acc.y += b.y; acc.z += b.z; acc.w += b.w;
    if (apply_act) {
        acc.x = lk(acc.x, act_slope);
        acc.y = lk(acc.y, act_slope);
        acc.z = lk(acc.z, act_slope);
        acc.w = lk(acc.w, act_slope);
    }
    reinterpret_cast<float4*>(out)[v * 32 + lane] = acc;
}

// ---------------------------------------------------------------------------
extern "C" void kernel_launch(void* const* d_in, const int* in_sizes, int n_in,
                              void* d_out, int out_size) {
    const float* x   = (const float*)d_in[0];
    const int*   src = (const int*)d_in[1];
    const int*   dst = (const int*)d_in[2];
    const float* W1  = (const float*)d_in[3];
    const float* al1 = (const float*)d_in[4];
    const float* ar1 = (const float*)d_in[5];
    const float* b1  = (const float*)d_in[6];
    const float* W2  = (const float*)d_in[7];
    const float* al2 = (const float*)d_in[8];
    const float* ar2 = (const float*)d_in[9];
    const float* b2  = (const float*)d_in[10];
    float* out = (float*)d_out;

    void* p_hid = nullptr;
    cudaGetSymbolAddress(&p_hid, g_hid);
    float* hid = (float*)p_hid;

    int eblocks = (EE + 255) / 256;
    int nblocks = (NN + 255) / 256;
    int gemm_blocks = (NN + 127) / 128;
    int gather_blocks = (NN + 7) / 8;       // 8 warps/block
    int off_blocks = (NN + 1023) / 1024;    // 49

    k_init<<<nblocks, 256>>>();                       // 1
    k_hist<<<eblocks, 256>>>(dst);                    // 2
    k_offsets<<<off_blocks, 1024>>>();                // 3
    k_gemm<<<gemm_blocks, 256>>>(x, W1, al1, ar1);    // 4  <- ncu capture slot
    k_scatter<<<eblocks, 256>>>(src, dst);            // 5
    k_gather<<<gather_blocks, 256>>>(b1, hid, 0.01f, 1);   // 6
    k_gemm<<<gemm_blocks, 256>>>(hid, W2, al2, ar2);       // 7
    k_gather<<<gather_blocks, 256>>>(b2, out, 0.0f, 0);    // 8
}